// round 13
// baseline (speedup 1.0000x reference)
#include <cuda_runtime.h>
#include <cuda_fp16.h>
#include <float.h>

#define N_NODES 50000
#define N_EDGES 1600000
#define F_HID   240
#define F_OUT   80
#define SCAN_B  256
#define SCAN_G  ((N_NODES + SCAN_B - 1) / SCAN_B)   // 196

#define CNT_SHIFT 42
#define DEG_MASK  ((1ULL << CNT_SHIFT) - 1)
#define DEG_SCALE (1.0f / 4294967296.0f)

// ---------------- scratch (device globals; no allocation allowed) ----------
__device__ unsigned long long g_degcnt[N_NODES];   // fixed-point deg | cnt<<42
__device__ unsigned long long g_scanst[SCAN_G];    // lookback: state<<62 | val
__device__ float  g_dis[N_NODES];
__device__ int    g_cnt[N_NODES];
__device__ int    g_off[N_NODES];
__device__ int    g_cur[N_NODES];
__device__ int2   g_edge[N_EDGES];                    // (src, nrm bits)
__device__ __half g_bufH[(size_t)N_NODES * F_HID];    // pre-agg features, fp16
__device__ __half g_aggH[(size_t)N_NODES * F_HID];    // agg outputs, fp16
__device__ __half g_W2h[F_HID * F_HID];               // W2 in fp16
__device__ __half g_Weh[F_HID * F_OUT];               // We in fp16

// ---------------- graph preprocessing --------------------------------------
__global__ void zero_kernel() {
    int i = blockIdx.x * blockDim.x + threadIdx.x;
    if (i < N_NODES) g_degcnt[i] = 0ULL;
    if (i < SCAN_G)  g_scanst[i] = 0ULL;
}

__device__ __forceinline__ unsigned long long pack_edge(float w) {
    return __float2ull_rn(w * 4294967296.0f) | (1ULL << CNT_SHIFT);
}

// 4 edges per thread, coalesced int4/float4 loads, packed 64-bit atomics
__global__ void deg_kernel(const int* __restrict__ ei,
                           const float* __restrict__ ew) {
    int t = blockIdx.x * blockDim.x + threadIdx.x;
    if (t < N_EDGES / 4) {
        int4   c4 = ((const int4*)(ei + N_EDGES))[t];
        float4 w4 = ((const float4*)ew)[t];
        if ((unsigned)c4.x < N_NODES) atomicAdd(&g_degcnt[c4.x], pack_edge(w4.x));
        if ((unsigned)c4.y < N_NODES) atomicAdd(&g_degcnt[c4.y], pack_edge(w4.y));
        if ((unsigned)c4.z < N_NODES) atomicAdd(&g_degcnt[c4.z], pack_edge(w4.z));
        if ((unsigned)c4.w < N_NODES) atomicAdd(&g_degcnt[c4.w], pack_edge(w4.w));
    }
}

// ---- single-pass decoupled-lookback exclusive scan of cnt ------------------
__global__ void scan_kernel() {
    __shared__ int s[SCAN_B];
    __shared__ int s_excl;
    int b = blockIdx.x, t = threadIdx.x;
    int i = b * SCAN_B + t;

    int cnt = 0;
    if (i < N_NODES) {
        unsigned long long p = g_degcnt[i];
        cnt = (int)(p >> CNT_SHIFT);
        g_dis[i] = rsqrtf((float)(p & DEG_MASK) * DEG_SCALE + 1.0f);
    }
    s[t] = cnt;
    __syncthreads();
    for (int d = 1; d < SCAN_B; d <<= 1) {
        int u = (t >= d) ? s[t - d] : 0;
        __syncthreads();
        s[t] += u;
        __syncthreads();
    }
    int incl = s[t];

    if (t == 0) {
        int total = s[SCAN_B - 1];
        if (b == 0) {
            s_excl = 0;
            atomicExch(&g_scanst[0], (2ULL << 62) | (unsigned)total);
        } else {
            atomicExch(&g_scanst[b], (1ULL << 62) | (unsigned)total);
            long long run = 0;
            int p = b - 1;
            while (true) {
                unsigned long long w = atomicAdd(&g_scanst[p], 0ULL);
                unsigned st = (unsigned)(w >> 62);
                if (st == 2u) { run += (unsigned)(w & 0xFFFFFFFFu); break; }
                if (st == 1u) { run += (unsigned)(w & 0xFFFFFFFFu); p--; }
            }
            s_excl = (int)run;
            atomicExch(&g_scanst[b], (2ULL << 62) | (unsigned)(run + total));
        }
    }
    __syncthreads();

    if (i < N_NODES) {
        int excl = s_excl + incl - cnt;
        g_off[i] = excl;
        g_cur[i] = excl;
        g_cnt[i] = cnt;
    }
}

// 2 edges per thread, vectorized reads
__global__ void fill_kernel(const int* __restrict__ ei,
                            const float* __restrict__ ew) {
    int t = blockIdx.x * blockDim.x + threadIdx.x;
    if (t < N_EDGES / 2) {
        int2   r2 = ((const int2*)ei)[t];
        int2   c2 = ((const int2*)(ei + N_EDGES))[t];
        float2 w2 = ((const float2*)ew)[t];
        if ((unsigned)r2.x < N_NODES && (unsigned)c2.x < N_NODES) {
            float nrm = g_dis[r2.x] * w2.x * g_dis[c2.x];
            int p = atomicAdd(&g_cur[c2.x], 1);
            g_edge[p] = make_int2(r2.x, __float_as_int(nrm));
        }
        if ((unsigned)r2.y < N_NODES && (unsigned)c2.y < N_NODES) {
            float nrm = g_dis[r2.y] * w2.y * g_dis[c2.y];
            int p = atomicAdd(&g_cur[c2.y], 1);
            g_edge[p] = make_int2(r2.y, __float_as_int(nrm));
        }
    }
}

// ---------------- weight fp16 conversion (once per launch) ------------------
__global__ void cvtW_kernel(const float* __restrict__ W2,
                            const float* __restrict__ We) {
    int i = blockIdx.x * blockDim.x + threadIdx.x;
    const int N2 = F_HID * F_HID / 4;
    const int NE = F_HID * F_OUT / 4;
    if (i < N2) {
        float4 v = ((const float4*)W2)[i];
        __half2 p0 = __floats2half2_rn(v.x, v.y);
        __half2 p1 = __floats2half2_rn(v.z, v.w);
        uint2 u; u.x = *(unsigned*)&p0; u.y = *(unsigned*)&p1;
        ((uint2*)g_W2h)[i] = u;
    } else if (i < N2 + NE) {
        int j = i - N2;
        float4 v = ((const float4*)We)[j];
        __half2 p0 = __floats2half2_rn(v.x, v.y);
        __half2 p1 = __floats2half2_rn(v.z, v.w);
        uint2 u; u.x = *(unsigned*)&p0; u.y = *(unsigned*)&p1;
        ((uint2*)g_Weh)[j] = u;
    }
}

// ---------------- GEMM1: [N,5] @ [5,240] -> g_bufH (fp16) ------------------
__global__ void gemm1_kernel(const float* __restrict__ x,
                             const float* __restrict__ W1) {
    int idx = blockIdx.x * blockDim.x + threadIdx.x;
    if (idx >= N_NODES * 60) return;
    int n = idx / 60, q = idx - n * 60;
    const float* xr = x + n * 5;
    float a0 = 0, a1 = 0, a2 = 0, a3 = 0;
#pragma unroll
    for (int k = 0; k < 5; k++) {
        float xv = xr[k];
        const float* w = W1 + k * F_HID + q * 4;
        a0 = fmaf(xv, w[0], a0);
        a1 = fmaf(xv, w[1], a1);
        a2 = fmaf(xv, w[2], a2);
        a3 = fmaf(xv, w[3], a3);
    }
    __half2 p0 = __floats2half2_rn(a0, a1);
    __half2 p1 = __floats2half2_rn(a2, a3);
    uint2 u;
    u.x = *(unsigned*)&p0;
    u.y = *(unsigned*)&p1;
    ((uint2*)g_bufH)[idx] = u;
}

// ---------------- scatter-max aggregation: WARP PER NODE --------------------
__global__ void __launch_bounds__(256, 8)
agg_kernel(const float* __restrict__ bias) {
    const uint4* __restrict__ hp   = (const uint4*)g_bufH;
    uint4* __restrict__       outh = (uint4*)g_aggH;

    int warp = threadIdx.x >> 5;
    int lane = threadIdx.x & 31;
    int n = blockIdx.x * 8 + warp;
    if (n >= N_NODES) return;
    int f = lane < 30 ? lane : 29;

    int   start = g_off[n];
    int   cnt   = g_cnt[n];
    float d     = g_dis[n];

    float4 vlo = make_float4(-FLT_MAX, -FLT_MAX, -FLT_MAX, -FLT_MAX);
    float4 vhi = vlo;

    const int2* __restrict__ ep = g_edge + start;
#pragma unroll 4
    for (int e = 0; e < cnt; e++) {
        int2   ed  = __ldg(&ep[e]);
        float  nrm = __int_as_float(ed.y);
        uint4  hv  = hp[(size_t)ed.x * 30 + f];
        float2 q0 = __half22float2(*(const __half2*)&hv.x);
        float2 q1 = __half22float2(*(const __half2*)&hv.y);
        float2 q2 = __half22float2(*(const __half2*)&hv.z);
        float2 q3 = __half22float2(*(const __half2*)&hv.w);
        vlo.x = fmaxf(vlo.x, nrm * q0.x);
        vlo.y = fmaxf(vlo.y, nrm * q0.y);
        vlo.z = fmaxf(vlo.z, nrm * q1.x);
        vlo.w = fmaxf(vlo.w, nrm * q1.y);
        vhi.x = fmaxf(vhi.x, nrm * q2.x);
        vhi.y = fmaxf(vhi.y, nrm * q2.y);
        vhi.z = fmaxf(vhi.z, nrm * q3.x);
        vhi.w = fmaxf(vhi.w, nrm * q3.y);
    }

    {   // self-loop term
        float  dd = d * d;
        uint4  hv = hp[(size_t)n * 30 + f];
        float2 q0 = __half22float2(*(const __half2*)&hv.x);
        float2 q1 = __half22float2(*(const __half2*)&hv.y);
        float2 q2 = __half22float2(*(const __half2*)&hv.z);
        float2 q3 = __half22float2(*(const __half2*)&hv.w);
        vlo.x = fmaxf(vlo.x, dd * q0.x);
        vlo.y = fmaxf(vlo.y, dd * q0.y);
        vlo.z = fmaxf(vlo.z, dd * q1.x);
        vlo.w = fmaxf(vlo.w, dd * q1.y);
        vhi.x = fmaxf(vhi.x, dd * q2.x);
        vhi.y = fmaxf(vhi.y, dd * q2.y);
        vhi.z = fmaxf(vhi.z, dd * q3.x);
        vhi.w = fmaxf(vhi.w, dd * q3.y);
    }

    if (lane < 30) {
        float4 b0 = ((const float4*)bias)[f * 2];
        float4 b1 = ((const float4*)bias)[f * 2 + 1];
        vlo.x = fmaxf(vlo.x + b0.x, 0.0f);
        vlo.y = fmaxf(vlo.y + b0.y, 0.0f);
        vlo.z = fmaxf(vlo.z + b0.z, 0.0f);
        vlo.w = fmaxf(vlo.w + b0.w, 0.0f);
        vhi.x = fmaxf(vhi.x + b1.x, 0.0f);
        vhi.y = fmaxf(vhi.y + b1.y, 0.0f);
        vhi.z = fmaxf(vhi.z + b1.z, 0.0f);
        vhi.w = fmaxf(vhi.w + b1.w, 0.0f);
        __half2 h0 = __floats2half2_rn(vlo.x, vlo.y);
        __half2 h1 = __floats2half2_rn(vlo.z, vlo.w);
        __half2 h2 = __floats2half2_rn(vhi.x, vhi.y);
        __half2 h3 = __floats2half2_rn(vhi.z, vhi.w);
        uint4 u;
        u.x = *(unsigned*)&h0; u.y = *(unsigned*)&h1;
        u.z = *(unsigned*)&h2; u.w = *(unsigned*)&h3;
        outh[(size_t)n * 30 + f] = u;
    }
}

// ---------------- HMMA GEMM: g_aggH[M,240] @ Wh[240,Nn], BK=48 --------------
#define AS_LD 56
#define BS_LD 88

__device__ __forceinline__ void ldsm_x4(unsigned (&r)[4], unsigned addr) {
    asm volatile("ldmatrix.sync.aligned.m8n8.x4.shared.b16 {%0,%1,%2,%3}, [%4];"
                 : "=r"(r[0]), "=r"(r[1]), "=r"(r[2]), "=r"(r[3]) : "r"(addr));
}
__device__ __forceinline__ void ldsm_x2t(unsigned (&r)[2], unsigned addr) {
    asm volatile("ldmatrix.sync.aligned.m8n8.x2.trans.shared.b16 {%0,%1}, [%2];"
                 : "=r"(r[0]), "=r"(r[1]) : "r"(addr));
}
__device__ __forceinline__ void mma16816(float (&c)[4], const unsigned (&a)[4],
                                         const unsigned (&b)[2]) {
    asm volatile(
        "mma.sync.aligned.m16n8k16.row.col.f32.f16.f16.f32 "
        "{%0,%1,%2,%3}, {%4,%5,%6,%7}, {%8,%9}, {%0,%1,%2,%3};"
        : "+f"(c[0]), "+f"(c[1]), "+f"(c[2]), "+f"(c[3])
        : "r"(a[0]), "r"(a[1]), "r"(a[2]), "r"(a[3]), "r"(b[0]), "r"(b[1]));
}

template <int DST>
__global__ void __launch_bounds__(256)
gemm_mma_kernel(const float* __restrict__ bias,
                float* __restrict__ Cout, int M) {
    __shared__ __half As[128 * AS_LD];
    __shared__ __half Bs[48 * BS_LD];

    const int Nn      = DST == 0 ? F_HID : F_OUT;
    const int BSTRIDE = Nn / 8;

    int tid  = threadIdx.x;
    int warp = tid >> 5;
    int lane = tid & 31;
    int wm = warp & 3;
    int wn = warp >> 2;
    int m0 = blockIdx.x * 128;
    int n0 = blockIdx.y * 80;

    const uint4* __restrict__ Ap = (const uint4*)g_aggH;
    const uint4* __restrict__ Bp = (const uint4*)(DST == 0 ? g_W2h : g_Weh);

    float acc[2][5][4];
#pragma unroll
    for (int i = 0; i < 2; i++)
#pragma unroll
        for (int j = 0; j < 5; j++)
#pragma unroll
            for (int k = 0; k < 4; k++) acc[i][j][k] = 0.0f;

    unsigned as_base = (unsigned)__cvta_generic_to_shared(As);
    unsigned bs_base = (unsigned)__cvta_generic_to_shared(Bs);
    int ai = lane & 7, as_sel = lane >> 3;
    int a_row_off = ai + ((as_sel & 1) ? 8 : 0);
    int a_k_sub   = (as_sel & 2) ? 8 : 0;
    int lane16 = lane & 15;

    for (int kt = 0; kt < 5; kt++) {
#pragma unroll
        for (int j = 0; j < 3; j++) {
            int i = tid + 256 * j;
            int row = i / 6, seg = i - row * 6;
            int grow = m0 + row;
            grow = grow < M ? grow : M - 1;
            uint4 v = Ap[(size_t)grow * 30 + kt * 6 + seg];
            *(uint4*)&As[row * AS_LD + seg * 8] = v;
        }
        if (tid < 160) {
#pragma unroll
            for (int j = 0; j < 3; j++) {
                int i = tid + 160 * j;
                int row = i / 10, seg = i - row * 10;
                uint4 v = Bp[(size_t)(kt * 48 + row) * BSTRIDE
                             + blockIdx.y * 10 + seg];
                *(uint4*)&Bs[row * BS_LD + seg * 8] = v;
            }
        }
        __syncthreads();

#pragma unroll
        for (int ks = 0; ks < 3; ks++) {
            unsigned afrag[2][4];
#pragma unroll
            for (int mt = 0; mt < 2; mt++) {
                int row = wm * 32 + mt * 16 + a_row_off;
                ldsm_x4(afrag[mt],
                        as_base + (unsigned)((row * AS_LD + ks * 16 + a_k_sub) * 2));
            }
#pragma unroll
            for (int nt = 0; nt < 5; nt++) {
                unsigned bfrag[2];
                int ncol = wn * 40 + nt * 8;
                ldsm_x2t(bfrag,
                         bs_base + (unsigned)(((ks * 16 + lane16) * BS_LD + ncol) * 2));
#pragma unroll
                for (int mt = 0; mt < 2; mt++)
                    mma16816(acc[mt][nt], afrag[mt], bfrag);
            }
        }
        __syncthreads();
    }

#pragma unroll
    for (int mt = 0; mt < 2; mt++) {
#pragma unroll
        for (int nt = 0; nt < 5; nt++) {
            int r0  = m0 + wm * 32 + mt * 16 + (lane >> 2);
            int col = n0 + wn * 40 + nt * 8 + (lane & 3) * 2;
            if (DST == 0) {
                if (r0 < M) {
                    __half2 h = __floats2half2_rn(acc[mt][nt][0], acc[mt][nt][1]);
                    *(__half2*)&g_bufH[(size_t)r0 * F_HID + col] = h;
                }
                int r1 = r0 + 8;
                if (r1 < M) {
                    __half2 h = __floats2half2_rn(acc[mt][nt][2], acc[mt][nt][3]);
                    *(__half2*)&g_bufH[(size_t)r1 * F_HID + col] = h;
                }
            } else {
                float bx = bias[col], by = bias[col + 1];
                if (r0 < M) {
                    float2 o = make_float2(acc[mt][nt][0] + bx, acc[mt][nt][1] + by);
                    *(float2*)&Cout[(size_t)r0 * F_OUT + col] = o;
                }
                int r1 = r0 + 8;
                if (r1 < M) {
                    float2 o = make_float2(acc[mt][nt][2] + bx, acc[mt][nt][3] + by);
                    *(float2*)&Cout[(size_t)r1 * F_OUT + col] = o;
                }
            }
        }
    }
}

// ---------------- launch ----------------------------------------------------
// Two branches forked from the capture stream:
//   main:  zero -> deg -> scan -> fill ----\
//   side:  gemm1 -> cvtW ------------------+--> agg1 -> gemm2 -> agg2 -> head
extern "C" void kernel_launch(void* const* d_in, const int* in_sizes, int n_in,
                              void* d_out, int out_size) {
    const float* x  = (const float*)d_in[0];
    const int*   ei = (const int*)d_in[1];     // int32 (JAX x64 disabled)
    const float* ew = (const float*)d_in[2];
    const float* W1 = (const float*)d_in[3];
    const float* b1 = (const float*)d_in[4];
    const float* W2 = (const float*)d_in[5];
    const float* b2 = (const float*)d_in[6];
    const float* We = (const float*)d_in[7];
    const float* be = (const float*)d_in[8];
    float* out = (float*)d_out;

    // side stream + events: created once on the (uncaptured) first call,
    // reused by the captured calls. Creation is host-side only.
    static cudaStream_t s_side = nullptr;
    static cudaEvent_t  ev_fork = nullptr, ev_join = nullptr;
    if (s_side == nullptr) {
        cudaStreamCreateWithFlags(&s_side, cudaStreamNonBlocking);
        cudaEventCreateWithFlags(&ev_fork, cudaEventDisableTiming);
        cudaEventCreateWithFlags(&ev_join, cudaEventDisableTiming);
    }

    const int TB = 256;
    int gN = (N_NODES + TB - 1) / TB;
    int gE4 = (N_EDGES / 4 + TB - 1) / TB;
    int gE2 = (N_EDGES / 2 + TB - 1) / TB;

    // fork
    cudaEventRecord(ev_fork, 0);
    cudaStreamWaitEvent(s_side, ev_fork, 0);

    // side branch: feature transform + weight conversion (graph-independent)
    gemm1_kernel<<<(N_NODES * 60 + TB - 1) / TB, TB, 0, s_side>>>(x, W1);
    cvtW_kernel<<<(F_HID * F_HID / 4 + F_HID * F_OUT / 4 + TB - 1) / TB, TB,
                  0, s_side>>>(W2, We);
    cudaEventRecord(ev_join, s_side);

    // main branch: graph structure
    zero_kernel<<<gN, TB>>>();
    deg_kernel<<<gE4, TB>>>(ei, ew);
    scan_kernel<<<SCAN_G, SCAN_B>>>();
    fill_kernel<<<gE2, TB>>>(ei, ew);

    // join
    cudaStreamWaitEvent(0, ev_join, 0);

    // layer 1 aggregation
    agg_kernel<<<(N_NODES + 7) / 8, 256>>>(b1);

    // layer 2 (tensor cores)
    {
        dim3 grid((N_NODES + 127) / 128, F_HID / 80);
        gemm_mma_kernel<0><<<grid, 256>>>(nullptr, nullptr, N_NODES);
    }
    agg_kernel<<<(N_NODES + 7) / 8, 256>>>(b2);

    // head (tensor cores, fp32 out)
    {
        dim3 grid((N_NODES + 127) / 128, 1);
        gemm_mma_kernel<1><<<grid, 256>>>(be, out, N_NODES);
    }
}

// round 14
// speedup vs baseline: 1.4692x; 1.4692x over previous
#include <cuda_runtime.h>
#include <cuda_fp16.h>
#include <float.h>

#define N_NODES 50000
#define N_EDGES 1600000
#define F_HID   240
#define F_OUT   80
#define SCAN_B  256
#define SCAN_G  ((N_NODES + SCAN_B - 1) / SCAN_B)   // 196

#define CNT_SHIFT 42
#define DEG_MASK  ((1ULL << CNT_SHIFT) - 1)
#define DEG_SCALE (1.0f / 4294967296.0f)

// ---------------- scratch (device globals; no allocation allowed) ----------
__device__ unsigned long long g_degcnt[N_NODES];   // fixed-point deg | cnt<<42
__device__ unsigned long long g_scanst[SCAN_G];    // lookback: state<<62 | val
__device__ float  g_dis[N_NODES];
__device__ int    g_cnt[N_NODES];
__device__ int    g_off[N_NODES];
__device__ int    g_cur[N_NODES];
__device__ int2   g_edge[N_EDGES];                    // (src, nrm bits)
__device__ __half g_bufH[(size_t)N_NODES * F_HID];    // pre-agg features, fp16
__device__ __half g_aggH[(size_t)N_NODES * F_HID];    // agg outputs, fp16
__device__ __half g_W2h[F_HID * F_HID];               // W2 in fp16
__device__ __half g_Weh[F_HID * F_OUT];               // We in fp16

// ---------------- graph preprocessing --------------------------------------
__global__ void zero_kernel() {
    int i = blockIdx.x * blockDim.x + threadIdx.x;
    if (i < N_NODES) g_degcnt[i] = 0ULL;
    if (i < SCAN_G)  g_scanst[i] = 0ULL;
}

__device__ __forceinline__ unsigned long long pack_edge(float w) {
    return __float2ull_rn(w * 4294967296.0f) | (1ULL << CNT_SHIFT);
}

// 4 edges per thread, coalesced int4/float4 loads, packed 64-bit atomics
__global__ void deg_kernel(const int* __restrict__ ei,
                           const float* __restrict__ ew) {
    int t = blockIdx.x * blockDim.x + threadIdx.x;
    if (t < N_EDGES / 4) {
        int4   c4 = ((const int4*)(ei + N_EDGES))[t];
        float4 w4 = ((const float4*)ew)[t];
        if ((unsigned)c4.x < N_NODES) atomicAdd(&g_degcnt[c4.x], pack_edge(w4.x));
        if ((unsigned)c4.y < N_NODES) atomicAdd(&g_degcnt[c4.y], pack_edge(w4.y));
        if ((unsigned)c4.z < N_NODES) atomicAdd(&g_degcnt[c4.z], pack_edge(w4.z));
        if ((unsigned)c4.w < N_NODES) atomicAdd(&g_degcnt[c4.w], pack_edge(w4.w));
    }
}

// ---- single-pass decoupled-lookback exclusive scan of cnt ------------------
__global__ void scan_kernel() {
    __shared__ int s[SCAN_B];
    __shared__ int s_excl;
    int b = blockIdx.x, t = threadIdx.x;
    int i = b * SCAN_B + t;

    int cnt = 0;
    if (i < N_NODES) {
        unsigned long long p = g_degcnt[i];
        cnt = (int)(p >> CNT_SHIFT);
        g_dis[i] = rsqrtf((float)(p & DEG_MASK) * DEG_SCALE + 1.0f);
    }
    s[t] = cnt;
    __syncthreads();
    for (int d = 1; d < SCAN_B; d <<= 1) {
        int u = (t >= d) ? s[t - d] : 0;
        __syncthreads();
        s[t] += u;
        __syncthreads();
    }
    int incl = s[t];

    if (t == 0) {
        int total = s[SCAN_B - 1];
        if (b == 0) {
            s_excl = 0;
            atomicExch(&g_scanst[0], (2ULL << 62) | (unsigned)total);
        } else {
            atomicExch(&g_scanst[b], (1ULL << 62) | (unsigned)total);
            long long run = 0;
            int p = b - 1;
            while (true) {
                unsigned long long w = atomicAdd(&g_scanst[p], 0ULL);
                unsigned st = (unsigned)(w >> 62);
                if (st == 2u) { run += (unsigned)(w & 0xFFFFFFFFu); break; }
                if (st == 1u) { run += (unsigned)(w & 0xFFFFFFFFu); p--; }
            }
            s_excl = (int)run;
            atomicExch(&g_scanst[b], (2ULL << 62) | (unsigned)(run + total));
        }
    }
    __syncthreads();

    if (i < N_NODES) {
        int excl = s_excl + incl - cnt;
        g_off[i] = excl;
        g_cur[i] = excl;
        g_cnt[i] = cnt;
    }
}

// 2 edges per thread, vectorized reads
__global__ void fill_kernel(const int* __restrict__ ei,
                            const float* __restrict__ ew) {
    int t = blockIdx.x * blockDim.x + threadIdx.x;
    if (t < N_EDGES / 2) {
        int2   r2 = ((const int2*)ei)[t];
        int2   c2 = ((const int2*)(ei + N_EDGES))[t];
        float2 w2 = ((const float2*)ew)[t];
        if ((unsigned)r2.x < N_NODES && (unsigned)c2.x < N_NODES) {
            float nrm = g_dis[r2.x] * w2.x * g_dis[c2.x];
            int p = atomicAdd(&g_cur[c2.x], 1);
            g_edge[p] = make_int2(r2.x, __float_as_int(nrm));
        }
        if ((unsigned)r2.y < N_NODES && (unsigned)c2.y < N_NODES) {
            float nrm = g_dis[r2.y] * w2.y * g_dis[c2.y];
            int p = atomicAdd(&g_cur[c2.y], 1);
            g_edge[p] = make_int2(r2.y, __float_as_int(nrm));
        }
    }
}

// ---------------- weight fp16 conversion (once per launch) ------------------
__global__ void cvtW_kernel(const float* __restrict__ W2,
                            const float* __restrict__ We) {
    int i = blockIdx.x * blockDim.x + threadIdx.x;
    const int N2 = F_HID * F_HID / 4;
    const int NE = F_HID * F_OUT / 4;
    if (i < N2) {
        float4 v = ((const float4*)W2)[i];
        __half2 p0 = __floats2half2_rn(v.x, v.y);
        __half2 p1 = __floats2half2_rn(v.z, v.w);
        uint2 u; u.x = *(unsigned*)&p0; u.y = *(unsigned*)&p1;
        ((uint2*)g_W2h)[i] = u;
    } else if (i < N2 + NE) {
        int j = i - N2;
        float4 v = ((const float4*)We)[j];
        __half2 p0 = __floats2half2_rn(v.x, v.y);
        __half2 p1 = __floats2half2_rn(v.z, v.w);
        uint2 u; u.x = *(unsigned*)&p0; u.y = *(unsigned*)&p1;
        ((uint2*)g_Weh)[j] = u;
    }
}

// ---------------- GEMM1: [N,5] @ [5,240] -> g_bufH (fp16) ------------------
__global__ void gemm1_kernel(const float* __restrict__ x,
                             const float* __restrict__ W1) {
    int idx = blockIdx.x * blockDim.x + threadIdx.x;
    if (idx >= N_NODES * 60) return;
    int n = idx / 60, q = idx - n * 60;
    const float* xr = x + n * 5;
    float a0 = 0, a1 = 0, a2 = 0, a3 = 0;
#pragma unroll
    for (int k = 0; k < 5; k++) {
        float xv = xr[k];
        const float* w = W1 + k * F_HID + q * 4;
        a0 = fmaf(xv, w[0], a0);
        a1 = fmaf(xv, w[1], a1);
        a2 = fmaf(xv, w[2], a2);
        a3 = fmaf(xv, w[3], a3);
    }
    __half2 p0 = __floats2half2_rn(a0, a1);
    __half2 p1 = __floats2half2_rn(a2, a3);
    uint2 u;
    u.x = *(unsigned*)&p0;
    u.y = *(unsigned*)&p1;
    ((uint2*)g_bufH)[idx] = u;
}

// ---------------- scatter-max aggregation: WARP PER NODE --------------------
__global__ void __launch_bounds__(256, 8)
agg_kernel(const float* __restrict__ bias) {
    const uint4* __restrict__ hp   = (const uint4*)g_bufH;
    uint4* __restrict__       outh = (uint4*)g_aggH;

    int warp = threadIdx.x >> 5;
    int lane = threadIdx.x & 31;
    int n = blockIdx.x * 8 + warp;
    if (n >= N_NODES) return;
    int f = lane < 30 ? lane : 29;

    int   start = g_off[n];
    int   cnt   = g_cnt[n];
    float d     = g_dis[n];

    float4 vlo = make_float4(-FLT_MAX, -FLT_MAX, -FLT_MAX, -FLT_MAX);
    float4 vhi = vlo;

    const int2* __restrict__ ep = g_edge + start;
#pragma unroll 4
    for (int e = 0; e < cnt; e++) {
        int2   ed  = __ldg(&ep[e]);
        float  nrm = __int_as_float(ed.y);
        uint4  hv  = hp[(size_t)ed.x * 30 + f];
        float2 q0 = __half22float2(*(const __half2*)&hv.x);
        float2 q1 = __half22float2(*(const __half2*)&hv.y);
        float2 q2 = __half22float2(*(const __half2*)&hv.z);
        float2 q3 = __half22float2(*(const __half2*)&hv.w);
        vlo.x = fmaxf(vlo.x, nrm * q0.x);
        vlo.y = fmaxf(vlo.y, nrm * q0.y);
        vlo.z = fmaxf(vlo.z, nrm * q1.x);
        vlo.w = fmaxf(vlo.w, nrm * q1.y);
        vhi.x = fmaxf(vhi.x, nrm * q2.x);
        vhi.y = fmaxf(vhi.y, nrm * q2.y);
        vhi.z = fmaxf(vhi.z, nrm * q3.x);
        vhi.w = fmaxf(vhi.w, nrm * q3.y);
    }

    {   // self-loop term
        float  dd = d * d;
        uint4  hv = hp[(size_t)n * 30 + f];
        float2 q0 = __half22float2(*(const __half2*)&hv.x);
        float2 q1 = __half22float2(*(const __half2*)&hv.y);
        float2 q2 = __half22float2(*(const __half2*)&hv.z);
        float2 q3 = __half22float2(*(const __half2*)&hv.w);
        vlo.x = fmaxf(vlo.x, dd * q0.x);
        vlo.y = fmaxf(vlo.y, dd * q0.y);
        vlo.z = fmaxf(vlo.z, dd * q1.x);
        vlo.w = fmaxf(vlo.w, dd * q1.y);
        vhi.x = fmaxf(vhi.x, dd * q2.x);
        vhi.y = fmaxf(vhi.y, dd * q2.y);
        vhi.z = fmaxf(vhi.z, dd * q3.x);
        vhi.w = fmaxf(vhi.w, dd * q3.y);
    }

    if (lane < 30) {
        float4 b0 = ((const float4*)bias)[f * 2];
        float4 b1 = ((const float4*)bias)[f * 2 + 1];
        vlo.x = fmaxf(vlo.x + b0.x, 0.0f);
        vlo.y = fmaxf(vlo.y + b0.y, 0.0f);
        vlo.z = fmaxf(vlo.z + b0.z, 0.0f);
        vlo.w = fmaxf(vlo.w + b0.w, 0.0f);
        vhi.x = fmaxf(vhi.x + b1.x, 0.0f);
        vhi.y = fmaxf(vhi.y + b1.y, 0.0f);
        vhi.z = fmaxf(vhi.z + b1.z, 0.0f);
        vhi.w = fmaxf(vhi.w + b1.w, 0.0f);
        __half2 h0 = __floats2half2_rn(vlo.x, vlo.y);
        __half2 h1 = __floats2half2_rn(vlo.z, vlo.w);
        __half2 h2 = __floats2half2_rn(vhi.x, vhi.y);
        __half2 h3 = __floats2half2_rn(vhi.z, vhi.w);
        uint4 u;
        u.x = *(unsigned*)&h0; u.y = *(unsigned*)&h1;
        u.z = *(unsigned*)&h2; u.w = *(unsigned*)&h3;
        outh[(size_t)n * 30 + f] = u;
    }
}

// ---------------- HMMA GEMM: g_aggH[M,240] @ Wh[240,Nn], BK=48 --------------
#define AS_LD 56
#define BS_LD 88

__device__ __forceinline__ void ldsm_x4(unsigned (&r)[4], unsigned addr) {
    asm volatile("ldmatrix.sync.aligned.m8n8.x4.shared.b16 {%0,%1,%2,%3}, [%4];"
                 : "=r"(r[0]), "=r"(r[1]), "=r"(r[2]), "=r"(r[3]) : "r"(addr));
}
__device__ __forceinline__ void ldsm_x2t(unsigned (&r)[2], unsigned addr) {
    asm volatile("ldmatrix.sync.aligned.m8n8.x2.trans.shared.b16 {%0,%1}, [%2];"
                 : "=r"(r[0]), "=r"(r[1]) : "r"(addr));
}
__device__ __forceinline__ void mma16816(float (&c)[4], const unsigned (&a)[4],
                                         const unsigned (&b)[2]) {
    asm volatile(
        "mma.sync.aligned.m16n8k16.row.col.f32.f16.f16.f32 "
        "{%0,%1,%2,%3}, {%4,%5,%6,%7}, {%8,%9}, {%0,%1,%2,%3};"
        : "+f"(c[0]), "+f"(c[1]), "+f"(c[2]), "+f"(c[3])
        : "r"(a[0]), "r"(a[1]), "r"(a[2]), "r"(a[3]), "r"(b[0]), "r"(b[1]));
}

template <int DST>
__global__ void __launch_bounds__(256)
gemm_mma_kernel(const float* __restrict__ bias,
                float* __restrict__ Cout, int M) {
    __shared__ __half As[128 * AS_LD];
    __shared__ __half Bs[48 * BS_LD];

    const int Nn      = DST == 0 ? F_HID : F_OUT;
    const int BSTRIDE = Nn / 8;

    int tid  = threadIdx.x;
    int warp = tid >> 5;
    int lane = tid & 31;
    int wm = warp & 3;
    int wn = warp >> 2;
    int m0 = blockIdx.x * 128;
    int n0 = blockIdx.y * 80;

    const uint4* __restrict__ Ap = (const uint4*)g_aggH;
    const uint4* __restrict__ Bp = (const uint4*)(DST == 0 ? g_W2h : g_Weh);

    float acc[2][5][4];
#pragma unroll
    for (int i = 0; i < 2; i++)
#pragma unroll
        for (int j = 0; j < 5; j++)
#pragma unroll
            for (int k = 0; k < 4; k++) acc[i][j][k] = 0.0f;

    unsigned as_base = (unsigned)__cvta_generic_to_shared(As);
    unsigned bs_base = (unsigned)__cvta_generic_to_shared(Bs);
    int ai = lane & 7, as_sel = lane >> 3;
    int a_row_off = ai + ((as_sel & 1) ? 8 : 0);
    int a_k_sub   = (as_sel & 2) ? 8 : 0;
    int lane16 = lane & 15;

    for (int kt = 0; kt < 5; kt++) {
#pragma unroll
        for (int j = 0; j < 3; j++) {
            int i = tid + 256 * j;
            int row = i / 6, seg = i - row * 6;
            int grow = m0 + row;
            grow = grow < M ? grow : M - 1;
            uint4 v = Ap[(size_t)grow * 30 + kt * 6 + seg];
            *(uint4*)&As[row * AS_LD + seg * 8] = v;
        }
        if (tid < 160) {
#pragma unroll
            for (int j = 0; j < 3; j++) {
                int i = tid + 160 * j;
                int row = i / 10, seg = i - row * 10;
                uint4 v = Bp[(size_t)(kt * 48 + row) * BSTRIDE
                             + blockIdx.y * 10 + seg];
                *(uint4*)&Bs[row * BS_LD + seg * 8] = v;
            }
        }
        __syncthreads();

#pragma unroll
        for (int ks = 0; ks < 3; ks++) {
            unsigned afrag[2][4];
#pragma unroll
            for (int mt = 0; mt < 2; mt++) {
                int row = wm * 32 + mt * 16 + a_row_off;
                ldsm_x4(afrag[mt],
                        as_base + (unsigned)((row * AS_LD + ks * 16 + a_k_sub) * 2));
            }
#pragma unroll
            for (int nt = 0; nt < 5; nt++) {
                unsigned bfrag[2];
                int ncol = wn * 40 + nt * 8;
                ldsm_x2t(bfrag,
                         bs_base + (unsigned)(((ks * 16 + lane16) * BS_LD + ncol) * 2));
#pragma unroll
                for (int mt = 0; mt < 2; mt++)
                    mma16816(acc[mt][nt], afrag[mt], bfrag);
            }
        }
        __syncthreads();
    }

#pragma unroll
    for (int mt = 0; mt < 2; mt++) {
#pragma unroll
        for (int nt = 0; nt < 5; nt++) {
            int r0  = m0 + wm * 32 + mt * 16 + (lane >> 2);
            int col = n0 + wn * 40 + nt * 8 + (lane & 3) * 2;
            if (DST == 0) {
                if (r0 < M) {
                    __half2 h = __floats2half2_rn(acc[mt][nt][0], acc[mt][nt][1]);
                    *(__half2*)&g_bufH[(size_t)r0 * F_HID + col] = h;
                }
                int r1 = r0 + 8;
                if (r1 < M) {
                    __half2 h = __floats2half2_rn(acc[mt][nt][2], acc[mt][nt][3]);
                    *(__half2*)&g_bufH[(size_t)r1 * F_HID + col] = h;
                }
            } else {
                float bx = bias[col], by = bias[col + 1];
                if (r0 < M) {
                    float2 o = make_float2(acc[mt][nt][0] + bx, acc[mt][nt][1] + by);
                    *(float2*)&Cout[(size_t)r0 * F_OUT + col] = o;
                }
                int r1 = r0 + 8;
                if (r1 < M) {
                    float2 o = make_float2(acc[mt][nt][2] + bx, acc[mt][nt][3] + by);
                    *(float2*)&Cout[(size_t)r1 * F_OUT + col] = o;
                }
            }
        }
    }
}

// ---------------- launch (single stream, R12 order) -------------------------
// Dataflow:
//   zero -> deg -> scan -> fill -> cvtW -> gemm1
//   -> agg1 -> gemm2(HMMA) -> agg2 -> head(HMMA)
extern "C" void kernel_launch(void* const* d_in, const int* in_sizes, int n_in,
                              void* d_out, int out_size) {
    const float* x  = (const float*)d_in[0];
    const int*   ei = (const int*)d_in[1];     // int32 (JAX x64 disabled)
    const float* ew = (const float*)d_in[2];
    const float* W1 = (const float*)d_in[3];
    const float* b1 = (const float*)d_in[4];
    const float* W2 = (const float*)d_in[5];
    const float* b2 = (const float*)d_in[6];
    const float* We = (const float*)d_in[7];
    const float* be = (const float*)d_in[8];
    float* out = (float*)d_out;

    const int TB = 256;
    int gN  = (N_NODES + TB - 1) / TB;
    int gE4 = (N_EDGES / 4 + TB - 1) / TB;
    int gE2 = (N_EDGES / 2 + TB - 1) / TB;

    // graph structure (shared by both layers)
    zero_kernel<<<gN, TB>>>();
    deg_kernel<<<gE4, TB>>>(ei, ew);
    scan_kernel<<<SCAN_G, SCAN_B>>>();
    fill_kernel<<<gE2, TB>>>(ei, ew);
    cvtW_kernel<<<(F_HID * F_HID / 4 + F_HID * F_OUT / 4 + TB - 1) / TB, TB>>>(W2, We);

    // layer 1
    gemm1_kernel<<<(N_NODES * 60 + TB - 1) / TB, TB>>>(x, W1);
    agg_kernel<<<(N_NODES + 7) / 8, 256>>>(b1);

    // layer 2 (tensor cores)
    {
        dim3 grid((N_NODES + 127) / 128, F_HID / 80);
        gemm_mma_kernel<0><<<grid, 256>>>(nullptr, nullptr, N_NODES);
    }
    agg_kernel<<<(N_NODES + 7) / 8, 256>>>(b2);

    // head (tensor cores, fp32 out)
    {
        dim3 grid((N_NODES + 127) / 128, 1);
        gemm_mma_kernel<1><<<grid, 256>>>(be, out, N_NODES);
    }
}

// round 15
// speedup vs baseline: 1.5033x; 1.0232x over previous
#include <cuda_runtime.h>
#include <cuda_fp16.h>
#include <float.h>

#define N_NODES 50000
#define N_EDGES 1600000
#define F_HID   240
#define F_OUT   80
#define SCAN_B  256
#define SCAN_G  ((N_NODES + SCAN_B - 1) / SCAN_B)   // 196

#define CNT_SHIFT 42
#define DEG_MASK  ((1ULL << CNT_SHIFT) - 1)
#define DEG_SCALE (1.0f / 4294967296.0f)

// fused pre-kernel block partition
#define GB_DEG  ((N_EDGES / 4 + 255) / 256)                   // 1563
#define GB_G1   ((N_NODES * 60 + 255) / 256)                  // 11719
#define GB_CVT  ((F_HID * F_HID / 4 + F_HID * F_OUT / 4 + 255) / 256)  // 75
#define GB_ALL  (GB_DEG + GB_G1 + GB_CVT)

// ---------------- scratch (device globals; no allocation allowed) ----------
// NOTE: zero-initialized at module load; scan_kernel re-zeroes g_degcnt and
// the fused pre-kernel re-zeroes g_scanst each run (self-cleaning replay).
__device__ unsigned long long g_degcnt[N_NODES];   // fixed-point deg | cnt<<42
__device__ unsigned long long g_scanst[SCAN_G];    // lookback: state<<62 | val
__device__ float  g_dis[N_NODES];
__device__ int    g_cnt[N_NODES];
__device__ int    g_off[N_NODES];
__device__ int    g_cur[N_NODES];
__device__ int2   g_edge[N_EDGES];                    // (src, nrm bits)
__device__ __half g_bufH[(size_t)N_NODES * F_HID];    // pre-agg features, fp16
__device__ __half g_aggH[(size_t)N_NODES * F_HID];    // agg outputs, fp16
__device__ __half g_W2h[F_HID * F_HID];               // W2 in fp16
__device__ __half g_Weh[F_HID * F_OUT];               // We in fp16

__device__ __forceinline__ unsigned long long pack_edge(float w) {
    return __float2ull_rn(w * 4294967296.0f) | (1ULL << CNT_SHIFT);
}

// ---------------- fused pre-kernel: deg + scanst-zero + gemm1 + cvtW --------
// Independent workloads partitioned by blockIdx; HW interleaves an
// atomic-bound job with fma/store-bound jobs (free concurrency, no streams).
__global__ void pre_kernel(const int* __restrict__ ei,
                           const float* __restrict__ ew,
                           const float* __restrict__ x,
                           const float* __restrict__ W1,
                           const float* __restrict__ W2,
                           const float* __restrict__ We) {
    int b   = blockIdx.x;
    int tid = threadIdx.x;

    if (b < GB_DEG) {
        // ---- degree accumulation (4 edges/thread) + g_scanst zeroing ----
        if (b == 0 && tid < SCAN_G) g_scanst[tid] = 0ULL;
        int t = b * 256 + tid;
        if (t < N_EDGES / 4) {
            int4   c4 = ((const int4*)(ei + N_EDGES))[t];
            float4 w4 = ((const float4*)ew)[t];
            if ((unsigned)c4.x < N_NODES) atomicAdd(&g_degcnt[c4.x], pack_edge(w4.x));
            if ((unsigned)c4.y < N_NODES) atomicAdd(&g_degcnt[c4.y], pack_edge(w4.y));
            if ((unsigned)c4.z < N_NODES) atomicAdd(&g_degcnt[c4.z], pack_edge(w4.z));
            if ((unsigned)c4.w < N_NODES) atomicAdd(&g_degcnt[c4.w], pack_edge(w4.w));
        }
    } else if (b < GB_DEG + GB_G1) {
        // ---- GEMM1: [N,5] @ [5,240] -> g_bufH (fp16) ----
        int idx = (b - GB_DEG) * 256 + tid;
        if (idx < N_NODES * 60) {
            int n = idx / 60, q = idx - n * 60;
            const float* xr = x + n * 5;
            float a0 = 0, a1 = 0, a2 = 0, a3 = 0;
#pragma unroll
            for (int k = 0; k < 5; k++) {
                float xv = xr[k];
                const float* w = W1 + k * F_HID + q * 4;
                a0 = fmaf(xv, w[0], a0);
                a1 = fmaf(xv, w[1], a1);
                a2 = fmaf(xv, w[2], a2);
                a3 = fmaf(xv, w[3], a3);
            }
            __half2 p0 = __floats2half2_rn(a0, a1);
            __half2 p1 = __floats2half2_rn(a2, a3);
            uint2 u;
            u.x = *(unsigned*)&p0;
            u.y = *(unsigned*)&p1;
            ((uint2*)g_bufH)[idx] = u;
        }
    } else {
        // ---- weight fp16 conversion ----
        int i = (b - GB_DEG - GB_G1) * 256 + tid;
        const int N2 = F_HID * F_HID / 4;
        const int NE = F_HID * F_OUT / 4;
        if (i < N2) {
            float4 v = ((const float4*)W2)[i];
            __half2 p0 = __floats2half2_rn(v.x, v.y);
            __half2 p1 = __floats2half2_rn(v.z, v.w);
            uint2 u; u.x = *(unsigned*)&p0; u.y = *(unsigned*)&p1;
            ((uint2*)g_W2h)[i] = u;
        } else if (i < N2 + NE) {
            int j = i - N2;
            float4 v = ((const float4*)We)[j];
            __half2 p0 = __floats2half2_rn(v.x, v.y);
            __half2 p1 = __floats2half2_rn(v.z, v.w);
            uint2 u; u.x = *(unsigned*)&p0; u.y = *(unsigned*)&p1;
            ((uint2*)g_Weh)[j] = u;
        }
    }
}

// ---- single-pass decoupled-lookback exclusive scan of cnt ------------------
// Reads + RE-ZEROES g_degcnt (so the next graph replay starts clean).
__global__ void scan_kernel() {
    __shared__ int s[SCAN_B];
    __shared__ int s_excl;
    int b = blockIdx.x, t = threadIdx.x;
    int i = b * SCAN_B + t;

    int cnt = 0;
    if (i < N_NODES) {
        unsigned long long p = g_degcnt[i];
        g_degcnt[i] = 0ULL;                       // self-clean for next replay
        cnt = (int)(p >> CNT_SHIFT);
        g_dis[i] = rsqrtf((float)(p & DEG_MASK) * DEG_SCALE + 1.0f);
    }
    s[t] = cnt;
    __syncthreads();
    for (int d = 1; d < SCAN_B; d <<= 1) {
        int u = (t >= d) ? s[t - d] : 0;
        __syncthreads();
        s[t] += u;
        __syncthreads();
    }
    int incl = s[t];

    if (t == 0) {
        int total = s[SCAN_B - 1];
        if (b == 0) {
            s_excl = 0;
            atomicExch(&g_scanst[0], (2ULL << 62) | (unsigned)total);
        } else {
            atomicExch(&g_scanst[b], (1ULL << 62) | (unsigned)total);
            long long run = 0;
            int p = b - 1;
            while (true) {
                unsigned long long w = atomicAdd(&g_scanst[p], 0ULL);
                unsigned st = (unsigned)(w >> 62);
                if (st == 2u) { run += (unsigned)(w & 0xFFFFFFFFu); break; }
                if (st == 1u) { run += (unsigned)(w & 0xFFFFFFFFu); p--; }
            }
            s_excl = (int)run;
            atomicExch(&g_scanst[b], (2ULL << 62) | (unsigned)(run + total));
        }
    }
    __syncthreads();

    if (i < N_NODES) {
        int excl = s_excl + incl - cnt;
        g_off[i] = excl;
        g_cur[i] = excl;
        g_cnt[i] = cnt;
    }
}

// 2 edges per thread, vectorized reads
__global__ void fill_kernel(const int* __restrict__ ei,
                            const float* __restrict__ ew) {
    int t = blockIdx.x * blockDim.x + threadIdx.x;
    if (t < N_EDGES / 2) {
        int2   r2 = ((const int2*)ei)[t];
        int2   c2 = ((const int2*)(ei + N_EDGES))[t];
        float2 w2 = ((const float2*)ew)[t];
        if ((unsigned)r2.x < N_NODES && (unsigned)c2.x < N_NODES) {
            float nrm = g_dis[r2.x] * w2.x * g_dis[c2.x];
            int p = atomicAdd(&g_cur[c2.x], 1);
            g_edge[p] = make_int2(r2.x, __float_as_int(nrm));
        }
        if ((unsigned)r2.y < N_NODES && (unsigned)c2.y < N_NODES) {
            float nrm = g_dis[r2.y] * w2.y * g_dis[c2.y];
            int p = atomicAdd(&g_cur[c2.y], 1);
            g_edge[p] = make_int2(r2.y, __float_as_int(nrm));
        }
    }
}

// ---------------- scatter-max aggregation: WARP PER NODE --------------------
__global__ void __launch_bounds__(256, 8)
agg_kernel(const float* __restrict__ bias) {
    const uint4* __restrict__ hp   = (const uint4*)g_bufH;
    uint4* __restrict__       outh = (uint4*)g_aggH;

    int warp = threadIdx.x >> 5;
    int lane = threadIdx.x & 31;
    int n = blockIdx.x * 8 + warp;
    if (n >= N_NODES) return;
    int f = lane < 30 ? lane : 29;

    int   start = g_off[n];
    int   cnt   = g_cnt[n];
    float d     = g_dis[n];

    float4 vlo = make_float4(-FLT_MAX, -FLT_MAX, -FLT_MAX, -FLT_MAX);
    float4 vhi = vlo;

    const int2* __restrict__ ep = g_edge + start;
#pragma unroll 4
    for (int e = 0; e < cnt; e++) {
        int2   ed  = __ldg(&ep[e]);
        float  nrm = __int_as_float(ed.y);
        uint4  hv  = hp[(size_t)ed.x * 30 + f];
        float2 q0 = __half22float2(*(const __half2*)&hv.x);
        float2 q1 = __half22float2(*(const __half2*)&hv.y);
        float2 q2 = __half22float2(*(const __half2*)&hv.z);
        float2 q3 = __half22float2(*(const __half2*)&hv.w);
        vlo.x = fmaxf(vlo.x, nrm * q0.x);
        vlo.y = fmaxf(vlo.y, nrm * q0.y);
        vlo.z = fmaxf(vlo.z, nrm * q1.x);
        vlo.w = fmaxf(vlo.w, nrm * q1.y);
        vhi.x = fmaxf(vhi.x, nrm * q2.x);
        vhi.y = fmaxf(vhi.y, nrm * q2.y);
        vhi.z = fmaxf(vhi.z, nrm * q3.x);
        vhi.w = fmaxf(vhi.w, nrm * q3.y);
    }

    {   // self-loop term
        float  dd = d * d;
        uint4  hv = hp[(size_t)n * 30 + f];
        float2 q0 = __half22float2(*(const __half2*)&hv.x);
        float2 q1 = __half22float2(*(const __half2*)&hv.y);
        float2 q2 = __half22float2(*(const __half2*)&hv.z);
        float2 q3 = __half22float2(*(const __half2*)&hv.w);
        vlo.x = fmaxf(vlo.x, dd * q0.x);
        vlo.y = fmaxf(vlo.y, dd * q0.y);
        vlo.z = fmaxf(vlo.z, dd * q1.x);
        vlo.w = fmaxf(vlo.w, dd * q1.y);
        vhi.x = fmaxf(vhi.x, dd * q2.x);
        vhi.y = fmaxf(vhi.y, dd * q2.y);
        vhi.z = fmaxf(vhi.z, dd * q3.x);
        vhi.w = fmaxf(vhi.w, dd * q3.y);
    }

    if (lane < 30) {
        float4 b0 = ((const float4*)bias)[f * 2];
        float4 b1 = ((const float4*)bias)[f * 2 + 1];
        vlo.x = fmaxf(vlo.x + b0.x, 0.0f);
        vlo.y = fmaxf(vlo.y + b0.y, 0.0f);
        vlo.z = fmaxf(vlo.z + b0.z, 0.0f);
        vlo.w = fmaxf(vlo.w + b0.w, 0.0f);
        vhi.x = fmaxf(vhi.x + b1.x, 0.0f);
        vhi.y = fmaxf(vhi.y + b1.y, 0.0f);
        vhi.z = fmaxf(vhi.z + b1.z, 0.0f);
        vhi.w = fmaxf(vhi.w + b1.w, 0.0f);
        __half2 h0 = __floats2half2_rn(vlo.x, vlo.y);
        __half2 h1 = __floats2half2_rn(vlo.z, vlo.w);
        __half2 h2 = __floats2half2_rn(vhi.x, vhi.y);
        __half2 h3 = __floats2half2_rn(vhi.z, vhi.w);
        uint4 u;
        u.x = *(unsigned*)&h0; u.y = *(unsigned*)&h1;
        u.z = *(unsigned*)&h2; u.w = *(unsigned*)&h3;
        outh[(size_t)n * 30 + f] = u;
    }
}

// ---------------- HMMA GEMM: g_aggH[M,240] @ Wh[240,Nn], BK=48 --------------
#define AS_LD 56
#define BS_LD 88

__device__ __forceinline__ void ldsm_x4(unsigned (&r)[4], unsigned addr) {
    asm volatile("ldmatrix.sync.aligned.m8n8.x4.shared.b16 {%0,%1,%2,%3}, [%4];"
                 : "=r"(r[0]), "=r"(r[1]), "=r"(r[2]), "=r"(r[3]) : "r"(addr));
}
__device__ __forceinline__ void ldsm_x2t(unsigned (&r)[2], unsigned addr) {
    asm volatile("ldmatrix.sync.aligned.m8n8.x2.trans.shared.b16 {%0,%1}, [%2];"
                 : "=r"(r[0]), "=r"(r[1]) : "r"(addr));
}
__device__ __forceinline__ void mma16816(float (&c)[4], const unsigned (&a)[4],
                                         const unsigned (&b)[2]) {
    asm volatile(
        "mma.sync.aligned.m16n8k16.row.col.f32.f16.f16.f32 "
        "{%0,%1,%2,%3}, {%4,%5,%6,%7}, {%8,%9}, {%0,%1,%2,%3};"
        : "+f"(c[0]), "+f"(c[1]), "+f"(c[2]), "+f"(c[3])
        : "r"(a[0]), "r"(a[1]), "r"(a[2]), "r"(a[3]), "r"(b[0]), "r"(b[1]));
}

template <int DST>
__global__ void __launch_bounds__(256)
gemm_mma_kernel(const float* __restrict__ bias,
                float* __restrict__ Cout, int M) {
    __shared__ __half As[128 * AS_LD];
    __shared__ __half Bs[48 * BS_LD];

    const int Nn      = DST == 0 ? F_HID : F_OUT;
    const int BSTRIDE = Nn / 8;

    int tid  = threadIdx.x;
    int warp = tid >> 5;
    int lane = tid & 31;
    int wm = warp & 3;
    int wn = warp >> 2;
    int m0 = blockIdx.x * 128;
    int n0 = blockIdx.y * 80;

    const uint4* __restrict__ Ap = (const uint4*)g_aggH;
    const uint4* __restrict__ Bp = (const uint4*)(DST == 0 ? g_W2h : g_Weh);

    float acc[2][5][4];
#pragma unroll
    for (int i = 0; i < 2; i++)
#pragma unroll
        for (int j = 0; j < 5; j++)
#pragma unroll
            for (int k = 0; k < 4; k++) acc[i][j][k] = 0.0f;

    unsigned as_base = (unsigned)__cvta_generic_to_shared(As);
    unsigned bs_base = (unsigned)__cvta_generic_to_shared(Bs);
    int ai = lane & 7, as_sel = lane >> 3;
    int a_row_off = ai + ((as_sel & 1) ? 8 : 0);
    int a_k_sub   = (as_sel & 2) ? 8 : 0;
    int lane16 = lane & 15;

    for (int kt = 0; kt < 5; kt++) {
#pragma unroll
        for (int j = 0; j < 3; j++) {
            int i = tid + 256 * j;
            int row = i / 6, seg = i - row * 6;
            int grow = m0 + row;
            grow = grow < M ? grow : M - 1;
            uint4 v = Ap[(size_t)grow * 30 + kt * 6 + seg];
            *(uint4*)&As[row * AS_LD + seg * 8] = v;
        }
        if (tid < 160) {
#pragma unroll
            for (int j = 0; j < 3; j++) {
                int i = tid + 160 * j;
                int row = i / 10, seg = i - row * 10;
                uint4 v = Bp[(size_t)(kt * 48 + row) * BSTRIDE
                             + blockIdx.y * 10 + seg];
                *(uint4*)&Bs[row * BS_LD + seg * 8] = v;
            }
        }
        __syncthreads();

#pragma unroll
        for (int ks = 0; ks < 3; ks++) {
            unsigned afrag[2][4];
#pragma unroll
            for (int mt = 0; mt < 2; mt++) {
                int row = wm * 32 + mt * 16 + a_row_off;
                ldsm_x4(afrag[mt],
                        as_base + (unsigned)((row * AS_LD + ks * 16 + a_k_sub) * 2));
            }
#pragma unroll
            for (int nt = 0; nt < 5; nt++) {
                unsigned bfrag[2];
                int ncol = wn * 40 + nt * 8;
                ldsm_x2t(bfrag,
                         bs_base + (unsigned)(((ks * 16 + lane16) * BS_LD + ncol) * 2));
#pragma unroll
                for (int mt = 0; mt < 2; mt++)
                    mma16816(acc[mt][nt], afrag[mt], bfrag);
            }
        }
        __syncthreads();
    }

#pragma unroll
    for (int mt = 0; mt < 2; mt++) {
#pragma unroll
        for (int nt = 0; nt < 5; nt++) {
            int r0  = m0 + wm * 32 + mt * 16 + (lane >> 2);
            int col = n0 + wn * 40 + nt * 8 + (lane & 3) * 2;
            if (DST == 0) {
                if (r0 < M) {
                    __half2 h = __floats2half2_rn(acc[mt][nt][0], acc[mt][nt][1]);
                    *(__half2*)&g_bufH[(size_t)r0 * F_HID + col] = h;
                }
                int r1 = r0 + 8;
                if (r1 < M) {
                    __half2 h = __floats2half2_rn(acc[mt][nt][2], acc[mt][nt][3]);
                    *(__half2*)&g_bufH[(size_t)r1 * F_HID + col] = h;
                }
            } else {
                float bx = bias[col], by = bias[col + 1];
                if (r0 < M) {
                    float2 o = make_float2(acc[mt][nt][0] + bx, acc[mt][nt][1] + by);
                    *(float2*)&Cout[(size_t)r0 * F_OUT + col] = o;
                }
                int r1 = r0 + 8;
                if (r1 < M) {
                    float2 o = make_float2(acc[mt][nt][2] + bx, acc[mt][nt][3] + by);
                    *(float2*)&Cout[(size_t)r1 * F_OUT + col] = o;
                }
            }
        }
    }
}

// ---------------- launch (single stream, 7 kernels) -------------------------
// Dataflow:
//   pre (deg + scanst-zero + gemm1 + cvtW, block-partitioned)
//   -> scan (also re-zeroes degcnt) -> fill
//   -> agg1 -> gemm2(HMMA) -> agg2 -> head(HMMA)
extern "C" void kernel_launch(void* const* d_in, const int* in_sizes, int n_in,
                              void* d_out, int out_size) {
    const float* x  = (const float*)d_in[0];
    const int*   ei = (const int*)d_in[1];     // int32 (JAX x64 disabled)
    const float* ew = (const float*)d_in[2];
    const float* W1 = (const float*)d_in[3];
    const float* b1 = (const float*)d_in[4];
    const float* W2 = (const float*)d_in[5];
    const float* b2 = (const float*)d_in[6];
    const float* We = (const float*)d_in[7];
    const float* be = (const float*)d_in[8];
    float* out = (float*)d_out;

    const int TB = 256;
    int gE2 = (N_EDGES / 2 + TB - 1) / TB;

    pre_kernel<<<GB_ALL, TB>>>(ei, ew, x, W1, W2, We);
    scan_kernel<<<SCAN_G, SCAN_B>>>();
    fill_kernel<<<gE2, TB>>>(ei, ew);

    agg_kernel<<<(N_NODES + 7) / 8, 256>>>(b1);

    {
        dim3 grid((N_NODES + 127) / 128, F_HID / 80);
        gemm_mma_kernel<0><<<grid, 256>>>(nullptr, nullptr, N_NODES);
    }
    agg_kernel<<<(N_NODES + 7) / 8, 256>>>(b2);

    {
        dim3 grid((N_NODES + 127) / 128, 1);
        gemm_mma_kernel<1><<<grid, 256>>>(be, out, N_NODES);
    }
}

// round 16
// speedup vs baseline: 1.7540x; 1.1668x over previous
#include <cuda_runtime.h>
#include <cuda_fp16.h>
#include <float.h>

#define N_NODES 50000
#define N_EDGES 1600000
#define F_HID   240
#define F_OUT   80
#define SCAN_B  256
#define SCAN_G  ((N_NODES + SCAN_B - 1) / SCAN_B)   // 196

#define CNT_SHIFT 42
#define DEG_MASK  ((1ULL << CNT_SHIFT) - 1)
#define DEG_SCALE (1.0f / 4294967296.0f)

// fused pre-kernel block partition
#define GB_DEG  ((N_EDGES / 4 + 255) / 256)                   // 1563
#define GB_G1   ((N_NODES * 60 + 255) / 256)                  // 11719
#define GB_CVT  ((F_HID * F_HID / 4 + F_HID * F_OUT / 4 + 255) / 256)  // 75
#define GB_ALL  (GB_DEG + GB_G1 + GB_CVT)

// ---------------- scratch (device globals; no allocation allowed) ----------
__device__ unsigned long long g_degcnt[N_NODES];   // fixed-point deg | cnt<<42
__device__ unsigned long long g_scanst[SCAN_G];    // lookback: state<<62 | val
__device__ float  g_dis[N_NODES];
__device__ int    g_cnt[N_NODES];
__device__ int    g_off[N_NODES];
__device__ int    g_cur[N_NODES];
__device__ int2   g_edge[N_EDGES];                    // (src, nrm as half2 bits)
__device__ __half g_bufH[(size_t)N_NODES * F_HID];    // pre-agg features, fp16
__device__ __half g_aggH[(size_t)N_NODES * F_HID];    // agg outputs, fp16
__device__ __half g_W2h[F_HID * F_HID];               // W2 in fp16
__device__ __half g_Weh[F_HID * F_OUT];               // We in fp16

__device__ __forceinline__ unsigned long long pack_edge(float w) {
    return __float2ull_rn(w * 4294967296.0f) | (1ULL << CNT_SHIFT);
}

// ---------------- fused pre-kernel: deg + scanst-zero + gemm1 + cvtW --------
__global__ void pre_kernel(const int* __restrict__ ei,
                           const float* __restrict__ ew,
                           const float* __restrict__ x,
                           const float* __restrict__ W1,
                           const float* __restrict__ W2,
                           const float* __restrict__ We) {
    int b   = blockIdx.x;
    int tid = threadIdx.x;

    if (b < GB_DEG) {
        if (b == 0 && tid < SCAN_G) g_scanst[tid] = 0ULL;
        int t = b * 256 + tid;
        if (t < N_EDGES / 4) {
            int4   c4 = ((const int4*)(ei + N_EDGES))[t];
            float4 w4 = ((const float4*)ew)[t];
            if ((unsigned)c4.x < N_NODES) atomicAdd(&g_degcnt[c4.x], pack_edge(w4.x));
            if ((unsigned)c4.y < N_NODES) atomicAdd(&g_degcnt[c4.y], pack_edge(w4.y));
            if ((unsigned)c4.z < N_NODES) atomicAdd(&g_degcnt[c4.z], pack_edge(w4.z));
            if ((unsigned)c4.w < N_NODES) atomicAdd(&g_degcnt[c4.w], pack_edge(w4.w));
        }
    } else if (b < GB_DEG + GB_G1) {
        int idx = (b - GB_DEG) * 256 + tid;
        if (idx < N_NODES * 60) {
            int n = idx / 60, q = idx - n * 60;
            const float* xr = x + n * 5;
            float a0 = 0, a1 = 0, a2 = 0, a3 = 0;
#pragma unroll
            for (int k = 0; k < 5; k++) {
                float xv = xr[k];
                const float* w = W1 + k * F_HID + q * 4;
                a0 = fmaf(xv, w[0], a0);
                a1 = fmaf(xv, w[1], a1);
                a2 = fmaf(xv, w[2], a2);
                a3 = fmaf(xv, w[3], a3);
            }
            __half2 p0 = __floats2half2_rn(a0, a1);
            __half2 p1 = __floats2half2_rn(a2, a3);
            uint2 u;
            u.x = *(unsigned*)&p0;
            u.y = *(unsigned*)&p1;
            ((uint2*)g_bufH)[idx] = u;
        }
    } else {
        int i = (b - GB_DEG - GB_G1) * 256 + tid;
        const int N2 = F_HID * F_HID / 4;
        const int NE = F_HID * F_OUT / 4;
        if (i < N2) {
            float4 v = ((const float4*)W2)[i];
            __half2 p0 = __floats2half2_rn(v.x, v.y);
            __half2 p1 = __floats2half2_rn(v.z, v.w);
            uint2 u; u.x = *(unsigned*)&p0; u.y = *(unsigned*)&p1;
            ((uint2*)g_W2h)[i] = u;
        } else if (i < N2 + NE) {
            int j = i - N2;
            float4 v = ((const float4*)We)[j];
            __half2 p0 = __floats2half2_rn(v.x, v.y);
            __half2 p1 = __floats2half2_rn(v.z, v.w);
            uint2 u; u.x = *(unsigned*)&p0; u.y = *(unsigned*)&p1;
            ((uint2*)g_Weh)[j] = u;
        }
    }
}

// ---- single-pass decoupled-lookback exclusive scan of cnt ------------------
__global__ void scan_kernel() {
    __shared__ int s[SCAN_B];
    __shared__ int s_excl;
    int b = blockIdx.x, t = threadIdx.x;
    int i = b * SCAN_B + t;

    int cnt = 0;
    if (i < N_NODES) {
        unsigned long long p = g_degcnt[i];
        g_degcnt[i] = 0ULL;                       // self-clean for next replay
        cnt = (int)(p >> CNT_SHIFT);
        g_dis[i] = rsqrtf((float)(p & DEG_MASK) * DEG_SCALE + 1.0f);
    }
    s[t] = cnt;
    __syncthreads();
    for (int d = 1; d < SCAN_B; d <<= 1) {
        int u = (t >= d) ? s[t - d] : 0;
        __syncthreads();
        s[t] += u;
        __syncthreads();
    }
    int incl = s[t];

    if (t == 0) {
        int total = s[SCAN_B - 1];
        if (b == 0) {
            s_excl = 0;
            atomicExch(&g_scanst[0], (2ULL << 62) | (unsigned)total);
        } else {
            atomicExch(&g_scanst[b], (1ULL << 62) | (unsigned)total);
            long long run = 0;
            int p = b - 1;
            while (true) {
                unsigned long long w = atomicAdd(&g_scanst[p], 0ULL);
                unsigned st = (unsigned)(w >> 62);
                if (st == 2u) { run += (unsigned)(w & 0xFFFFFFFFu); break; }
                if (st == 1u) { run += (unsigned)(w & 0xFFFFFFFFu); p--; }
            }
            s_excl = (int)run;
            atomicExch(&g_scanst[b], (2ULL << 62) | (unsigned)(run + total));
        }
    }
    __syncthreads();

    if (i < N_NODES) {
        int excl = s_excl + incl - cnt;
        g_off[i] = excl;
        g_cur[i] = excl;
        g_cnt[i] = cnt;
    }
}

// 2 edges per thread; nrm pre-converted to half2 (agg does zero converts)
__global__ void fill_kernel(const int* __restrict__ ei,
                            const float* __restrict__ ew) {
    int t = blockIdx.x * blockDim.x + threadIdx.x;
    if (t < N_EDGES / 2) {
        int2   r2 = ((const int2*)ei)[t];
        int2   c2 = ((const int2*)(ei + N_EDGES))[t];
        float2 w2 = ((const float2*)ew)[t];
        if ((unsigned)r2.x < N_NODES && (unsigned)c2.x < N_NODES) {
            float nrm = g_dis[r2.x] * w2.x * g_dis[c2.x];
            __half2 nh = __float2half2_rn(nrm);
            int p = atomicAdd(&g_cur[c2.x], 1);
            g_edge[p] = make_int2(r2.x, *(int*)&nh);
        }
        if ((unsigned)r2.y < N_NODES && (unsigned)c2.y < N_NODES) {
            float nrm = g_dis[r2.y] * w2.y * g_dis[c2.y];
            __half2 nh = __float2half2_rn(nrm);
            int p = atomicAdd(&g_cur[c2.y], 1);
            g_edge[p] = make_int2(r2.y, *(int*)&nh);
        }
    }
}

// ---------------- scatter-max aggregation: WARP PER NODE, fp16 math ---------
// Per edge: 1 broadcast int2 load, 1 uint4 gather, 4 hmul2 + 4 hmax2.
// 32-bit addressing (feature arrays are 24 MB). Max in fp16 is exact;
// product picks up one fp16 rounding (inputs already fp16).
__global__ void __launch_bounds__(256, 8)
agg_kernel(const float* __restrict__ bias) {
    const uint4* __restrict__ hp   = (const uint4*)g_bufH;
    uint4* __restrict__       outh = (uint4*)g_aggH;

    int warp = threadIdx.x >> 5;
    int lane = threadIdx.x & 31;
    int n = blockIdx.x * 8 + warp;
    if (n >= N_NODES) return;
    unsigned f = lane < 30 ? (unsigned)lane : 29u;

    int   start = g_off[n];
    int   cnt   = g_cnt[n];
    float d     = g_dis[n];

    const __half NEG = __ushort_as_half((unsigned short)0xFC00);  // -inf
    __half2 v0 = __halves2half2(NEG, NEG);
    __half2 v1 = v0, v2 = v0, v3 = v0;

    const int2* __restrict__ ep = g_edge + start;
#pragma unroll 4
    for (int e = 0; e < cnt; e++) {
        int2    ed = __ldg(&ep[e]);
        __half2 nh = *(__half2*)&ed.y;
        uint4   hv = hp[(unsigned)ed.x * 30u + f];
        v0 = __hmax2(v0, __hmul2(nh, *(__half2*)&hv.x));
        v1 = __hmax2(v1, __hmul2(nh, *(__half2*)&hv.y));
        v2 = __hmax2(v2, __hmul2(nh, *(__half2*)&hv.z));
        v3 = __hmax2(v3, __hmul2(nh, *(__half2*)&hv.w));
    }

    {   // self-loop term: dis[n]^2 * h[n]
        __half2 dh = __float2half2_rn(d * d);
        uint4   hv = hp[(unsigned)n * 30u + f];
        v0 = __hmax2(v0, __hmul2(dh, *(__half2*)&hv.x));
        v1 = __hmax2(v1, __hmul2(dh, *(__half2*)&hv.y));
        v2 = __hmax2(v2, __hmul2(dh, *(__half2*)&hv.z));
        v3 = __hmax2(v3, __hmul2(dh, *(__half2*)&hv.w));
    }

    if (lane < 30) {
        // epilogue in fp32: +bias, relu, pack back to fp16
        float2 q0 = __half22float2(v0);
        float2 q1 = __half22float2(v1);
        float2 q2 = __half22float2(v2);
        float2 q3 = __half22float2(v3);
        float4 b0 = ((const float4*)bias)[f * 2];
        float4 b1 = ((const float4*)bias)[f * 2 + 1];
        q0.x = fmaxf(q0.x + b0.x, 0.0f);
        q0.y = fmaxf(q0.y + b0.y, 0.0f);
        q1.x = fmaxf(q1.x + b0.z, 0.0f);
        q1.y = fmaxf(q1.y + b0.w, 0.0f);
        q2.x = fmaxf(q2.x + b1.x, 0.0f);
        q2.y = fmaxf(q2.y + b1.y, 0.0f);
        q3.x = fmaxf(q3.x + b1.z, 0.0f);
        q3.y = fmaxf(q3.y + b1.w, 0.0f);
        __half2 h0 = __floats2half2_rn(q0.x, q0.y);
        __half2 h1 = __floats2half2_rn(q1.x, q1.y);
        __half2 h2 = __floats2half2_rn(q2.x, q2.y);
        __half2 h3 = __floats2half2_rn(q3.x, q3.y);
        uint4 u;
        u.x = *(unsigned*)&h0; u.y = *(unsigned*)&h1;
        u.z = *(unsigned*)&h2; u.w = *(unsigned*)&h3;
        outh[(unsigned)n * 30u + f] = u;
    }
}

// ---------------- HMMA GEMM: g_aggH[M,240] @ Wh[240,Nn], BK=48 --------------
#define AS_LD 56
#define BS_LD 88

__device__ __forceinline__ void ldsm_x4(unsigned (&r)[4], unsigned addr) {
    asm volatile("ldmatrix.sync.aligned.m8n8.x4.shared.b16 {%0,%1,%2,%3}, [%4];"
                 : "=r"(r[0]), "=r"(r[1]), "=r"(r[2]), "=r"(r[3]) : "r"(addr));
}
__device__ __forceinline__ void ldsm_x2t(unsigned (&r)[2], unsigned addr) {
    asm volatile("ldmatrix.sync.aligned.m8n8.x2.trans.shared.b16 {%0,%1}, [%2];"
                 : "=r"(r[0]), "=r"(r[1]) : "r"(addr));
}
__device__ __forceinline__ void mma16816(float (&c)[4], const unsigned (&a)[4],
                                         const unsigned (&b)[2]) {
    asm volatile(
        "mma.sync.aligned.m16n8k16.row.col.f32.f16.f16.f32 "
        "{%0,%1,%2,%3}, {%4,%5,%6,%7}, {%8,%9}, {%0,%1,%2,%3};"
        : "+f"(c[0]), "+f"(c[1]), "+f"(c[2]), "+f"(c[3])
        : "r"(a[0]), "r"(a[1]), "r"(a[2]), "r"(a[3]), "r"(b[0]), "r"(b[1]));
}

template <int DST>
__global__ void __launch_bounds__(256)
gemm_mma_kernel(const float* __restrict__ bias,
                float* __restrict__ Cout, int M) {
    __shared__ __half As[128 * AS_LD];
    __shared__ __half Bs[48 * BS_LD];

    const int Nn      = DST == 0 ? F_HID : F_OUT;
    const int BSTRIDE = Nn / 8;

    int tid  = threadIdx.x;
    int warp = tid >> 5;
    int lane = tid & 31;
    int wm = warp & 3;
    int wn = warp >> 2;
    int m0 = blockIdx.x * 128;
    int n0 = blockIdx.y * 80;

    const uint4* __restrict__ Ap = (const uint4*)g_aggH;
    const uint4* __restrict__ Bp = (const uint4*)(DST == 0 ? g_W2h : g_Weh);

    float acc[2][5][4];
#pragma unroll
    for (int i = 0; i < 2; i++)
#pragma unroll
        for (int j = 0; j < 5; j++)
#pragma unroll
            for (int k = 0; k < 4; k++) acc[i][j][k] = 0.0f;

    unsigned as_base = (unsigned)__cvta_generic_to_shared(As);
    unsigned bs_base = (unsigned)__cvta_generic_to_shared(Bs);
    int ai = lane & 7, as_sel = lane >> 3;
    int a_row_off = ai + ((as_sel & 1) ? 8 : 0);
    int a_k_sub   = (as_sel & 2) ? 8 : 0;
    int lane16 = lane & 15;

    for (int kt = 0; kt < 5; kt++) {
#pragma unroll
        for (int j = 0; j < 3; j++) {
            int i = tid + 256 * j;
            int row = i / 6, seg = i - row * 6;
            int grow = m0 + row;
            grow = grow < M ? grow : M - 1;
            uint4 v = Ap[(size_t)grow * 30 + kt * 6 + seg];
            *(uint4*)&As[row * AS_LD + seg * 8] = v;
        }
        if (tid < 160) {
#pragma unroll
            for (int j = 0; j < 3; j++) {
                int i = tid + 160 * j;
                int row = i / 10, seg = i - row * 10;
                uint4 v = Bp[(size_t)(kt * 48 + row) * BSTRIDE
                             + blockIdx.y * 10 + seg];
                *(uint4*)&Bs[row * BS_LD + seg * 8] = v;
            }
        }
        __syncthreads();

#pragma unroll
        for (int ks = 0; ks < 3; ks++) {
            unsigned afrag[2][4];
#pragma unroll
            for (int mt = 0; mt < 2; mt++) {
                int row = wm * 32 + mt * 16 + a_row_off;
                ldsm_x4(afrag[mt],
                        as_base + (unsigned)((row * AS_LD + ks * 16 + a_k_sub) * 2));
            }
#pragma unroll
            for (int nt = 0; nt < 5; nt++) {
                unsigned bfrag[2];
                int ncol = wn * 40 + nt * 8;
                ldsm_x2t(bfrag,
                         bs_base + (unsigned)(((ks * 16 + lane16) * BS_LD + ncol) * 2));
#pragma unroll
                for (int mt = 0; mt < 2; mt++)
                    mma16816(acc[mt][nt], afrag[mt], bfrag);
            }
        }
        __syncthreads();
    }

#pragma unroll
    for (int mt = 0; mt < 2; mt++) {
#pragma unroll
        for (int nt = 0; nt < 5; nt++) {
            int r0  = m0 + wm * 32 + mt * 16 + (lane >> 2);
            int col = n0 + wn * 40 + nt * 8 + (lane & 3) * 2;
            if (DST == 0) {
                if (r0 < M) {
                    __half2 h = __floats2half2_rn(acc[mt][nt][0], acc[mt][nt][1]);
                    *(__half2*)&g_bufH[(size_t)r0 * F_HID + col] = h;
                }
                int r1 = r0 + 8;
                if (r1 < M) {
                    __half2 h = __floats2half2_rn(acc[mt][nt][2], acc[mt][nt][3]);
                    *(__half2*)&g_bufH[(size_t)r1 * F_HID + col] = h;
                }
            } else {
                float bx = bias[col], by = bias[col + 1];
                if (r0 < M) {
                    float2 o = make_float2(acc[mt][nt][0] + bx, acc[mt][nt][1] + by);
                    *(float2*)&Cout[(size_t)r0 * F_OUT + col] = o;
                }
                int r1 = r0 + 8;
                if (r1 < M) {
                    float2 o = make_float2(acc[mt][nt][2] + bx, acc[mt][nt][3] + by);
                    *(float2*)&Cout[(size_t)r1 * F_OUT + col] = o;
                }
            }
        }
    }
}

// ---------------- launch (single stream, 7 kernels) -------------------------
extern "C" void kernel_launch(void* const* d_in, const int* in_sizes, int n_in,
                              void* d_out, int out_size) {
    const float* x  = (const float*)d_in[0];
    const int*   ei = (const int*)d_in[1];     // int32 (JAX x64 disabled)
    const float* ew = (const float*)d_in[2];
    const float* W1 = (const float*)d_in[3];
    const float* b1 = (const float*)d_in[4];
    const float* W2 = (const float*)d_in[5];
    const float* b2 = (const float*)d_in[6];
    const float* We = (const float*)d_in[7];
    const float* be = (const float*)d_in[8];
    float* out = (float*)d_out;

    const int TB = 256;
    int gE2 = (N_EDGES / 2 + TB - 1) / TB;

    pre_kernel<<<GB_ALL, TB>>>(ei, ew, x, W1, W2, We);
    scan_kernel<<<SCAN_G, SCAN_B>>>();
    fill_kernel<<<gE2, TB>>>(ei, ew);

    agg_kernel<<<(N_NODES + 7) / 8, 256>>>(b1);

    {
        dim3 grid((N_NODES + 127) / 128, F_HID / 80);
        gemm_mma_kernel<0><<<grid, 256>>>(nullptr, nullptr, N_NODES);
    }
    agg_kernel<<<(N_NODES + 7) / 8, 256>>>(b2);

    {
        dim3 grid((N_NODES + 127) / 128, 1);
        gemm_mma_kernel<1><<<grid, 256>>>(be, out, N_NODES);
    }
}